// round 1
// baseline (speedup 1.0000x reference)
#include <cuda_runtime.h>
#include <cstdint>

#define D_A     1024
#define D_Bc    1024
#define RNK     16
#define NEXP    64
#define BATCH   256
#define POOL_DIM 33792
#define U_END   16384
#define V_END   32768
#define KEXT    1088   /* 1024 (n,r) + 64 bias cols */
#define LN_EPS  1e-5f

// ---------------- scratch (device globals; no allocs allowed) ----------------
__device__ __align__(128) float g_Bmat[KEXT * D_Bc];   // [k][c]  4.46 MB
__device__ __align__(128) float g_S[BATCH * KEXT];     // [b][k]  1.11 MB
__device__ __align__(128) float g_P[BATCH * D_Bc];     // h_A @ W_base^T
__device__ __align__(128) float g_X[BATCH * D_A];      // pre-LN activations

// ---------------- helpers ----------------
__device__ __forceinline__ void cpa16(void* smem_ptr, const void* gptr) {
    uint32_t s = (uint32_t)__cvta_generic_to_shared(smem_ptr);
    asm volatile("cp.async.cg.shared.global [%0], [%1], 16;\n" :: "r"(s), "l"(gptr));
}
__device__ __forceinline__ void cp_commit() { asm volatile("cp.async.commit_group;\n"); }
template<int N> __device__ __forceinline__ void cp_wait() {
    asm volatile("cp.async.wait_group %0;\n" :: "n"(N));
}
__device__ __forceinline__ void mma_tf32(float* c, const uint32_t* a, const uint32_t* b) {
    asm volatile(
        "mma.sync.aligned.m16n8k8.row.col.f32.tf32.tf32.f32 "
        "{%0,%1,%2,%3}, {%4,%5,%6,%7}, {%8,%9}, {%0,%1,%2,%3};\n"
        : "+f"(c[0]), "+f"(c[1]), "+f"(c[2]), "+f"(c[3])
        : "r"(a[0]), "r"(a[1]), "r"(a[2]), "r"(a[3]), "r"(b[0]), "r"(b[1]));
}

// ---------------- prep: Bmat[k][c] = U[n,c,r] (transposed via smem), bias rows,
// ---------------- and alpha columns of S ----------------
__global__ void __launch_bounds__(256) prep_kernel(const float* __restrict__ pool,
                                                   const float* __restrict__ alpha) {
    __shared__ __align__(16) float sU[512 * 17];
    const int n   = blockIdx.x;          // 0..63
    const int tid = threadIdx.x;         // 0..255
    const float* pn = pool + (size_t)n * POOL_DIM;

    #pragma unroll
    for (int h = 0; h < 2; h++) {
        #pragma unroll
        for (int i = 0; i < 32; i++) {          // load 8192 floats, coalesced
            int l = tid + i * 256;              // l = c_local*16 + r
            sU[l + (l >> 4)] = pn[h * 8192 + l];  // -> sU[c_local*17 + r]
        }
        __syncthreads();
        #pragma unroll
        for (int i = 0; i < 32; i++) {          // write 16 rows of 512 cols, coalesced
            int e = tid + i * 256;
            int r = e >> 9;                     // 0..15
            int c = e & 511;                    // 0..511
            g_Bmat[(n * 16 + r) * D_Bc + h * 512 + c] = sU[c * 17 + r];
        }
        __syncthreads();
    }
    // bias row: Bmat[1024+n][c] = pool[n, V_END + c]
    #pragma unroll
    for (int i = 0; i < 4; i++) {
        int c = tid + i * 256;
        g_Bmat[(1024 + n) * D_Bc + c] = pn[V_END + c];
    }
    // alpha columns of S: S[b][1024+n] = alpha[b,n]
    g_S[tid * KEXT + 1024 + n] = alpha[tid * NEXP + n];
}

// ---------------- GEMM1: C[256,2048] = h_A(256x1024) * M^T ----------------
// M rows: j<1024 -> W_base[j][:]; j>=1024 -> V[n,r,:] in pool.
// Epilogue: cols <1024 -> g_P; cols >=1024 -> g_S = t * alpha[b, n].
__global__ void __launch_bounds__(128) gemm1_kernel(const float* __restrict__ hA,
                                                    const float* __restrict__ W,
                                                    const float* __restrict__ pool,
                                                    const float* __restrict__ alpha) {
    __shared__ __align__(16) float As[4][64][20];
    __shared__ __align__(16) float Bs[4][64][20];

    const int tid  = threadIdx.x;
    const int bn   = blockIdx.x;     // 0..31
    const int bm   = blockIdx.y;     // 0..3
    const int lane = tid & 31, warp = tid >> 5;
    const int g = lane >> 2, tig = lane & 3;
    const int wm = warp & 1, wn = warp >> 1;

    // copy mapping: thread handles rows cm and cm+32, float4 slot kq
    const int cm = tid >> 2;      // 0..31
    const int kq = tid & 3;       // 0..3
    const float* srcA0 = hA + (size_t)(bm * 64 + cm) * D_A + kq * 4;
    const float* srcA1 = srcA0 + (size_t)32 * D_A;
    const int j0 = bn * 64 + cm;
    const int j1 = j0 + 32;
    const float* srcB0 = (j0 < 1024)
        ? (W + (size_t)j0 * D_A)
        : (pool + (size_t)((j0 - 1024) >> 4) * POOL_DIM + U_END + (size_t)((j0 - 1024) & 15) * D_A);
    const float* srcB1 = (j1 < 1024)
        ? (W + (size_t)j1 * D_A)
        : (pool + (size_t)((j1 - 1024) >> 4) * POOL_DIM + U_END + (size_t)((j1 - 1024) & 15) * D_A);
    srcB0 += kq * 4; srcB1 += kq * 4;

    float acc[2][4][4];
    #pragma unroll
    for (int i = 0; i < 2; i++)
        #pragma unroll
        for (int j = 0; j < 4; j++)
            #pragma unroll
            for (int e = 0; e < 4; e++) acc[i][j][e] = 0.f;

    const int NK = 64;   // 1024 / 16
    auto load_stage = [&](int s, int kc) {
        int off = kc * 16;
        cpa16(&As[s][cm][kq * 4],      srcA0 + off);
        cpa16(&As[s][cm + 32][kq * 4], srcA1 + off);
        cpa16(&Bs[s][cm][kq * 4],      srcB0 + off);
        cpa16(&Bs[s][cm + 32][kq * 4], srcB1 + off);
    };
    #pragma unroll
    for (int p = 0; p < 3; p++) { load_stage(p, p); cp_commit(); }

    for (int i = 0; i < NK; i++) {
        cp_wait<2>();
        __syncthreads();
        if (i + 3 < NK) load_stage((i + 3) & 3, i + 3);
        cp_commit();
        const int s = i & 3;
        #pragma unroll
        for (int kk = 0; kk < 2; kk++) {
            const int k0 = kk * 8;
            uint32_t a[2][4], b[4][2];
            #pragma unroll
            for (int im = 0; im < 2; im++) {
                const float* Ab = &As[s][wm * 32 + im * 16][k0 + tig];
                a[im][0] = __float_as_uint(Ab[g * 20]);
                a[im][1] = __float_as_uint(Ab[(g + 8) * 20]);
                a[im][2] = __float_as_uint(Ab[g * 20 + 4]);
                a[im][3] = __float_as_uint(Ab[(g + 8) * 20 + 4]);
            }
            #pragma unroll
            for (int jn = 0; jn < 4; jn++) {
                const float* Bb = &Bs[s][wn * 32 + jn * 8 + g][k0 + tig];
                b[jn][0] = __float_as_uint(Bb[0]);
                b[jn][1] = __float_as_uint(Bb[4]);
            }
            #pragma unroll
            for (int im = 0; im < 2; im++)
                #pragma unroll
                for (int jn = 0; jn < 4; jn++)
                    mma_tf32(acc[im][jn], a[im], b[jn]);
        }
    }

    // epilogue
    const int rbase = bm * 64 + wm * 32;
    const int cbase = bn * 64 + wn * 32;
    if (bn < 16) {
        #pragma unroll
        for (int im = 0; im < 2; im++)
            #pragma unroll
            for (int jn = 0; jn < 4; jn++) {
                int r = rbase + im * 16 + g;
                int c = cbase + jn * 8 + 2 * tig;
                g_P[r * D_Bc + c]           = acc[im][jn][0];
                g_P[r * D_Bc + c + 1]       = acc[im][jn][1];
                g_P[(r + 8) * D_Bc + c]     = acc[im][jn][2];
                g_P[(r + 8) * D_Bc + c + 1] = acc[im][jn][3];
            }
    } else {
        #pragma unroll
        for (int im = 0; im < 2; im++)
            #pragma unroll
            for (int jn = 0; jn < 4; jn++) {
                int r = rbase + im * 16 + g;
                int k = cbase + jn * 8 + 2 * tig - 1024;   // k even -> k,k+1 same n
                int nidx = k >> 4;
                float al0 = alpha[r * NEXP + nidx];
                float al8 = alpha[(r + 8) * NEXP + nidx];
                g_S[r * KEXT + k]           = acc[im][jn][0] * al0;
                g_S[r * KEXT + k + 1]       = acc[im][jn][1] * al0;
                g_S[(r + 8) * KEXT + k]     = acc[im][jn][2] * al8;
                g_S[(r + 8) * KEXT + k + 1] = acc[im][jn][3] * al8;
            }
    }
}

// ---------------- GEMM2: acc[b,c] = S(256x1088) * Bmat(1088x1024);
// epilogue: x = h_A + gamma*(acc + P + b_base) -> g_X ----------------
__global__ void __launch_bounds__(128) gemm2_kernel(const float* __restrict__ hA,
                                                    const float* __restrict__ bbase,
                                                    const float* __restrict__ gamma_p) {
    __shared__ __align__(16) float As[4][64][20];
    __shared__ __align__(16) float Bs[4][16][68];

    const int tid  = threadIdx.x;
    const int bn   = blockIdx.x;     // 0..15
    const int bm   = blockIdx.y;     // 0..3
    const int lane = tid & 31, warp = tid >> 5;
    const int g = lane >> 2, tig = lane & 3;
    const int wm = warp & 1, wn = warp >> 1;

    // A copy mapping
    const int cm = tid >> 2;      // 0..31
    const int kq = tid & 3;
    const float* srcA0 = g_S + (size_t)(bm * 64 + cm) * KEXT + kq * 4;
    const float* srcA1 = srcA0 + (size_t)32 * KEXT;
    // B copy mapping: rows k (16 per stage), 64 cols
    const int k0r = tid >> 4;     // 0..7
    const int cq  = tid & 15;     // 0..15
    const float* srcB0 = g_Bmat + (size_t)k0r * D_Bc + bn * 64 + cq * 4;
    const float* srcB1 = srcB0 + (size_t)8 * D_Bc;

    float acc[2][4][4];
    #pragma unroll
    for (int i = 0; i < 2; i++)
        #pragma unroll
        for (int j = 0; j < 4; j++)
            #pragma unroll
            for (int e = 0; e < 4; e++) acc[i][j][e] = 0.f;

    const int NK = 68;   // 1088 / 16
    auto load_stage = [&](int s, int kc) {
        int offA = kc * 16;
        size_t offB = (size_t)kc * 16 * D_Bc;
        cpa16(&As[s][cm][kq * 4],       srcA0 + offA);
        cpa16(&As[s][cm + 32][kq * 4],  srcA1 + offA);
        cpa16(&Bs[s][k0r][cq * 4],      srcB0 + offB);
        cpa16(&Bs[s][k0r + 8][cq * 4],  srcB1 + offB);
    };
    #pragma unroll
    for (int p = 0; p < 3; p++) { load_stage(p, p); cp_commit(); }

    for (int i = 0; i < NK; i++) {
        cp_wait<2>();
        __syncthreads();
        if (i + 3 < NK) load_stage((i + 3) & 3, i + 3);
        cp_commit();
        const int s = i & 3;
        #pragma unroll
        for (int kk = 0; kk < 2; kk++) {
            const int k0 = kk * 8;
            uint32_t a[2][4], b[4][2];
            #pragma unroll
            for (int im = 0; im < 2; im++) {
                const float* Ab = &As[s][wm * 32 + im * 16][k0 + tig];
                a[im][0] = __float_as_uint(Ab[g * 20]);
                a[im][1] = __float_as_uint(Ab[(g + 8) * 20]);
                a[im][2] = __float_as_uint(Ab[g * 20 + 4]);
                a[im][3] = __float_as_uint(Ab[(g + 8) * 20 + 4]);
            }
            #pragma unroll
            for (int jn = 0; jn < 4; jn++) {
                int col = wn * 32 + jn * 8 + g;
                b[jn][0] = __float_as_uint(Bs[s][k0 + tig][col]);
                b[jn][1] = __float_as_uint(Bs[s][k0 + tig + 4][col]);
            }
            #pragma unroll
            for (int im = 0; im < 2; im++)
                #pragma unroll
                for (int jn = 0; jn < 4; jn++)
                    mma_tf32(acc[im][jn], a[im], b[jn]);
        }
    }

    const float gam = *gamma_p;
    const int rbase = bm * 64 + wm * 32;
    const int cbase = bn * 64 + wn * 32;
    #pragma unroll
    for (int im = 0; im < 2; im++)
        #pragma unroll
        for (int jn = 0; jn < 4; jn++) {
            int r = rbase + im * 16 + g;
            int c = cbase + jn * 8 + 2 * tig;
            #pragma unroll
            for (int dr = 0; dr < 2; dr++) {
                int rr = r + dr * 8;
                #pragma unroll
                for (int dc = 0; dc < 2; dc++) {
                    int cc = c + dc;
                    float v = acc[im][jn][dr * 2 + dc];
                    float pre = v + g_P[rr * D_Bc + cc] + bbase[cc];
                    g_X[rr * D_Bc + cc] = hA[rr * D_A + cc] + gam * pre;
                }
            }
        }
}

// ---------------- LayerNorm: one block per row ----------------
__global__ void __launch_bounds__(256) ln_kernel(const float* __restrict__ lns,
                                                 const float* __restrict__ lnb,
                                                 float* __restrict__ out) {
    const int row = blockIdx.x;
    const int tid = threadIdx.x;
    float4 v = reinterpret_cast<const float4*>(g_X + (size_t)row * D_A)[tid];
    float s  = v.x + v.y + v.z + v.w;
    float ss = v.x * v.x + v.y * v.y + v.z * v.z + v.w * v.w;
    #pragma unroll
    for (int o = 16; o; o >>= 1) {
        s  += __shfl_xor_sync(0xffffffffu, s, o);
        ss += __shfl_xor_sync(0xffffffffu, ss, o);
    }
    __shared__ float rs[8], rss[8];
    __shared__ float mv[2];
    const int w = tid >> 5, l = tid & 31;
    if (l == 0) { rs[w] = s; rss[w] = ss; }
    __syncthreads();
    if (tid == 0) {
        float S = 0.f, SS = 0.f;
        #pragma unroll
        for (int i = 0; i < 8; i++) { S += rs[i]; SS += rss[i]; }
        float mean = S * (1.f / 1024.f);
        float var  = SS * (1.f / 1024.f) - mean * mean;
        mv[0] = mean;
        mv[1] = rsqrtf(var + LN_EPS);
    }
    __syncthreads();
    const float mean = mv[0], inv = mv[1];
    float4 sc = reinterpret_cast<const float4*>(lns)[tid];
    float4 bi = reinterpret_cast<const float4*>(lnb)[tid];
    float4 o;
    o.x = (v.x - mean) * inv * sc.x + bi.x;
    o.y = (v.y - mean) * inv * sc.y + bi.y;
    o.z = (v.z - mean) * inv * sc.z + bi.z;
    o.w = (v.w - mean) * inv * sc.w + bi.w;
    reinterpret_cast<float4*>(out + (size_t)row * D_A)[tid] = o;
}

// ---------------- launch ----------------
extern "C" void kernel_launch(void* const* d_in, const int* in_sizes, int n_in,
                              void* d_out, int out_size) {
    const float* hA    = (const float*)d_in[0];
    const float* pool  = (const float*)d_in[1];
    const float* alpha = (const float*)d_in[2];
    const float* W     = (const float*)d_in[3];
    const float* bb    = (const float*)d_in[4];
    const float* gamma = (const float*)d_in[5];
    const float* lns   = (const float*)d_in[6];
    const float* lnb   = (const float*)d_in[7];
    float* out = (float*)d_out;

    prep_kernel<<<64, 256>>>(pool, alpha);
    gemm1_kernel<<<dim3(32, 4), 128>>>(hA, W, pool, alpha);
    gemm2_kernel<<<dim3(16, 4), 128>>>(hA, bb, gamma);
    ln_kernel<<<256, 256>>>(lns, lnb, out);
}

// round 5
// speedup vs baseline: 1.2131x; 1.2131x over previous
#include <cuda_runtime.h>
#include <cstdint>

#define D_A      1024
#define NEXP     64
#define BATCH    256
#define POOL_DIM 33792
#define U_END    16384
#define V_END    32768
#define KEXT     1088
#define LN_EPS   1e-5f

#define NK1 32            /* 1024/32 */
#define NK2 34            /* 1088/32 */
#define A_STG 8192        /* 64 rows x 128B */
#define B_STG1 8192       /* 64 rows x 128B */
#define B_STG2 4096       /* 32 rows x 128B */
#define EP1 72            /* epi stride floats */
#define EP2 40

// ---------------- scratch ----------------
__device__ __align__(128) float  g_BmatT[(size_t)1024 * KEXT];  // [c][k]
__device__ __align__(128) float  g_S[BATCH * KEXT];             // [b][k]
__device__ __align__(128) float  g_P[BATCH * 1024];
__device__ __align__(128) float  g_X[BATCH * 1024];
__device__ __align__(128) float2 g_part[BATCH * 32];            // [row][bn]

// ---------------- helpers ----------------
__device__ __forceinline__ uint32_t smem_u32(const void* p) {
    uint32_t a;
    asm("{ .reg .u64 t; cvta.to.shared.u64 t, %1; cvt.u32.u64 %0, t; }" : "=r"(a) : "l"(p));
    return a;
}
__device__ __forceinline__ uint32_t swz(uint32_t off) { return off ^ ((off >> 3) & 0x70); }
__device__ __forceinline__ void cpa16(uint32_t saddr, const void* g) {
    asm volatile("cp.async.cg.shared.global [%0], [%1], 16;\n" :: "r"(saddr), "l"(g));
}
__device__ __forceinline__ void cp_commit() { asm volatile("cp.async.commit_group;\n"); }
template<int N> __device__ __forceinline__ void cp_wait() {
    asm volatile("cp.async.wait_group %0;\n" :: "n"(N));
}
#define LDSM4(R, addr) \
    asm volatile("ldmatrix.sync.aligned.m8n8.x4.shared.b16 {%0,%1,%2,%3}, [%4];" \
        : "=r"((R)[0]), "=r"((R)[1]), "=r"((R)[2]), "=r"((R)[3]) : "r"(addr))
__device__ __forceinline__ void mma_tf32(float* c, const uint32_t* a, const uint32_t* b) {
    asm volatile(
        "mma.sync.aligned.m16n8k8.row.col.f32.tf32.tf32.f32 "
        "{%0,%1,%2,%3}, {%4,%5,%6,%7}, {%8,%9}, {%0,%1,%2,%3};\n"
        : "+f"(c[0]), "+f"(c[1]), "+f"(c[2]), "+f"(c[3])
        : "r"(a[0]), "r"(a[1]), "r"(a[2]), "r"(a[3]), "r"(b[0]), "r"(b[1]));
}

// ---------------- prep role (128 threads): g_BmatT + alpha cols of g_S ------
__device__ void prep_role(int pid, float* sf, const float* __restrict__ pool,
                          const float* __restrict__ alpha) {
    const int tid = threadIdx.x;
    if (pid == 32) {   // alpha columns of S
        #pragma unroll 8
        for (int it = 0; it < 128; it++) {
            int e = tid + it * 128;
            int b = e >> 6, n = e & 63;
            g_S[(size_t)b * KEXT + 1024 + n] = alpha[b * NEXP + n];
        }
        return;
    }
    const int c0 = pid * 32;
    for (int ng = 0; ng < 4; ng++) {
        #pragma unroll
        for (int it = 0; it < 16; it++) {
            int e = tid + it * 128;
            int nl = e >> 7, i4 = e & 127;
            const float4* src = (const float4*)(pool + (size_t)(ng * 16 + nl) * POOL_DIM + c0 * 16) + i4;
            *(float4*)(sf + nl * 528 + i4 * 4) = *src;
        }
        __syncthreads();
        #pragma unroll 8
        for (int it = 0; it < 64; it++) {
            int e = tid + it * 128;
            int cl = e >> 8, j = e & 255;
            int nl = j >> 4, r = j & 15;
            g_BmatT[(size_t)(c0 + cl) * KEXT + ng * 256 + j] = sf[nl * 528 + cl * 16 + r];
        }
        __syncthreads();
    }
    #pragma unroll
    for (int it = 0; it < 16; it++) {
        int e = tid + it * 128;
        int n = e >> 5, cl = e & 31;
        sf[n * 33 + cl] = pool[(size_t)n * POOL_DIM + V_END + c0 + cl];
    }
    __syncthreads();
    #pragma unroll
    for (int it = 0; it < 16; it++) {
        int e = tid + it * 128;
        int cl = e >> 6, n = e & 63;
        g_BmatT[(size_t)(c0 + cl) * KEXT + 1024 + n] = sf[n * 33 + cl];
    }
}

// ---------------- k1: blocks 0..32 prep; 33..160 GEMM1 (64x64 tiles) --------
// C[256,2048] = h_A * [W_base | V]^T ; cols<1024 -> g_P, cols>=1024 -> g_S*alpha
__global__ void __launch_bounds__(128) k1_kernel(const float* __restrict__ hA,
                                                 const float* __restrict__ W,
                                                 const float* __restrict__ pool,
                                                 const float* __restrict__ alpha) {
    __shared__ __align__(128) float smem_all[8448];   // 33792 B (static, <48KB)
    const int bid = blockIdx.x;
    if (bid < 33) { prep_role(bid, smem_all, pool, alpha); return; }

    const uint32_t sb = smem_u32(smem_all);
    const int gb = bid - 33;
    const int bm = gb >> 5;           // 0..3
    const int bn = gb & 31;           // 0..31
    const int tid = threadIdx.x;
    const int lane = tid & 31, warp = tid >> 5;
    const int wm = warp & 1, wn = warp >> 1;
    const int g = lane >> 2, tig = lane & 3;

    const uint32_t sbA = sb;                  // 2 stages x 8192
    const uint32_t sbB = sb + 2 * A_STG;      // 2 stages x 8192

    // cp.async maps (4 chunks each side per thread)
    const float* aPtr[4]; uint32_t aDst[4];
    const float* bPtr[4]; uint32_t bDst[4];
    #pragma unroll
    for (int q = 0; q < 4; q++) {
        int id = tid + q * 128;
        int row = id >> 3, c8 = id & 7;
        aPtr[q] = hA + (size_t)(bm * 64 + row) * D_A + c8 * 4;
        aDst[q] = swz(row * 128 + c8 * 16);
        int j = bn * 64 + row;
        const float* base = (bn < 16)
            ? (W + (size_t)j * D_A)
            : (pool + (size_t)((j - 1024) >> 4) * POOL_DIM + U_END + (size_t)((j - 1024) & 15) * D_A);
        bPtr[q] = base + c8 * 4;
        bDst[q] = swz(row * 128 + c8 * 16);
    }
    auto fill = [&](int s, int kc) {
        const int off = kc * 32;
        #pragma unroll
        for (int q = 0; q < 4; q++) {
            cpa16(sbA + s * A_STG + aDst[q], aPtr[q] + off);
            cpa16(sbB + s * B_STG1 + bDst[q], bPtr[q] + off);
        }
    };

    // ldmatrix address precompute
    uint32_t aBase[2], aXor[2], bBase[2], bXor[2];
    const uint32_t ahi = ((lane >> 4) & 1) * 16;
    const uint32_t bhi = ((lane >> 3) & 1) * 16;
    #pragma unroll
    for (int im = 0; im < 2; im++) {
        int r = wm * 32 + im * 16 + (lane & 7) + ((lane >> 3) & 1) * 8;
        aBase[im] = r * 128; aXor[im] = (r & 7) << 4;
    }
    #pragma unroll
    for (int jp = 0; jp < 2; jp++) {
        int r = wn * 32 + jp * 16 + (lane & 7) + ((lane >> 4) & 1) * 8;
        bBase[jp] = r * 128; bXor[jp] = (r & 7) << 4;
    }

    float acc[2][4][4];
    #pragma unroll
    for (int i = 0; i < 2; i++)
        #pragma unroll
        for (int j = 0; j < 4; j++)
            #pragma unroll
            for (int e = 0; e < 4; e++) acc[i][j][e] = 0.f;

    fill(0, 0); cp_commit();

    for (int i = 0; i < NK1; i++) {
        if (i + 1 < NK1) { fill((i + 1) & 1, i + 1); cp_commit(); cp_wait<1>(); }
        else             { cp_wait<0>(); }
        __syncthreads();
        const int s = i & 1;
        const uint32_t sA = sbA + s * A_STG;
        const uint32_t sB = sbB + s * B_STG1;
        #pragma unroll
        for (int kk = 0; kk < 4; kk++) {
            uint32_t a[2][4], b[2][4];
            #pragma unroll
            for (int im = 0; im < 2; im++)
                LDSM4(a[im], sA + aBase[im] + ((kk * 32 + ahi) ^ aXor[im]));
            #pragma unroll
            for (int jp = 0; jp < 2; jp++)
                LDSM4(b[jp], sB + bBase[jp] + ((kk * 32 + bhi) ^ bXor[jp]));
            #pragma unroll
            for (int im = 0; im < 2; im++)
                #pragma unroll
                for (int jn = 0; jn < 4; jn++)
                    mma_tf32(acc[im][jn], a[im], &b[jn >> 1][(jn & 1) * 2]);
        }
        __syncthreads();
    }

    // stage accumulators through smem, then coalesced float4 out
    float* se = smem_all;
    #pragma unroll
    for (int im = 0; im < 2; im++)
        #pragma unroll
        for (int jn = 0; jn < 4; jn++) {
            int r0 = wm * 32 + im * 16 + g;
            int c  = wn * 32 + jn * 8 + 2 * tig;
            se[r0 * EP1 + c]           = acc[im][jn][0];
            se[r0 * EP1 + c + 1]       = acc[im][jn][1];
            se[(r0 + 8) * EP1 + c]     = acc[im][jn][2];
            se[(r0 + 8) * EP1 + c + 1] = acc[im][jn][3];
        }
    __syncthreads();
    #pragma unroll
    for (int it = 0; it < 8; it++) {
        int id = tid + it * 128;
        int row = id >> 4, c4 = id & 15;
        float4 v = *(const float4*)(se + row * EP1 + c4 * 4);
        int rowg = bm * 64 + row;
        if (bn < 16) {
            ((float4*)g_P)[(size_t)rowg * 256 + bn * 16 + c4] = v;
        } else {
            int n = (bn - 16) * 4 + (c4 >> 2);
            float a = alpha[rowg * NEXP + n];
            v.x *= a; v.y *= a; v.z *= a; v.w *= a;
            ((float4*)g_S)[(size_t)rowg * 272 + (bn - 16) * 16 + c4] = v;
        }
    }
}

// ---------------- k2: GEMM2 64x32 tiles; X = hA + gamma*(S@BmatT^T + P + b) --
__global__ void __launch_bounds__(128) k2_kernel(const float* __restrict__ hA,
                                                 const float* __restrict__ bbase,
                                                 const float* __restrict__ gamma_p) {
    __shared__ __align__(128) float smem_all[6144];   // 24576 B
    const uint32_t sb = smem_u32(smem_all);
    const int bid = blockIdx.x;
    const int bm = bid >> 5;          // 0..3
    const int bn = bid & 31;          // 0..31
    const int tid = threadIdx.x;
    const int lane = tid & 31, warp = tid >> 5;
    const int wm = warp & 1, wn = warp >> 1;
    const int g = lane >> 2, tig = lane & 3;

    const uint32_t sbA = sb;                  // 2 stages x 8192
    const uint32_t sbB = sb + 2 * A_STG;      // 2 stages x 4096

    const float* aPtr[4]; uint32_t aDst[4];
    #pragma unroll
    for (int q = 0; q < 4; q++) {
        int id = tid + q * 128;
        int row = id >> 3, c8 = id & 7;
        aPtr[q] = g_S + (size_t)(bm * 64 + row) * KEXT + c8 * 4;
        aDst[q] = swz(row * 128 + c8 * 16);
    }
    const float* bPtr[2]; uint32_t bDst[2];
    #pragma unroll
    for (int q = 0; q < 2; q++) {
        int id = tid + q * 128;
        int row = id >> 3, c8 = id & 7;
        bPtr[q] = g_BmatT + (size_t)(bn * 32 + row) * KEXT + c8 * 4;
        bDst[q] = swz(row * 128 + c8 * 16);
    }
    auto fill = [&](int s, int kc) {
        const int off = kc * 32;
        #pragma unroll
        for (int q = 0; q < 4; q++)
            cpa16(sbA + s * A_STG + aDst[q], aPtr[q] + off);
        #pragma unroll
        for (int q = 0; q < 2; q++)
            cpa16(sbB + s * B_STG2 + bDst[q], bPtr[q] + off);
    };

    uint32_t aBase[2], aXor[2], bBase, bXor;
    const uint32_t ahi = ((lane >> 4) & 1) * 16;
    const uint32_t bhi = ((lane >> 3) & 1) * 16;
    #pragma unroll
    for (int im = 0; im < 2; im++) {
        int r = wm * 32 + im * 16 + (lane & 7) + ((lane >> 3) & 1) * 8;
        aBase[im] = r * 128; aXor[im] = (r & 7) << 4;
    }
    {
        int r = wn * 16 + (lane & 7) + ((lane >> 4) & 1) * 8;
        bBase = r * 128; bXor = (r & 7) << 4;
    }

    float acc[2][2][4];
    #pragma unroll
    for (int i = 0; i < 2; i++)
        #pragma unroll
        for (int j = 0; j < 2; j++)
            #pragma unroll
            for (int e = 0; e < 4; e++) acc[i][j][e] = 0.f;

    fill(0, 0); cp_commit();

    for (int i = 0; i < NK2; i++) {
        if (i + 1 < NK2) { fill((i + 1) & 1, i + 1); cp_commit(); cp_wait<1>(); }
        else             { cp_wait<0>(); }
        __syncthreads();
        const int s = i & 1;
        const uint32_t sA = sbA + s * A_STG;
        const uint32_t sB = sbB + s * B_STG2;
        #pragma unroll
        for (int kk = 0; kk < 4; kk++) {
            uint32_t a[2][4], b[4];
            #pragma unroll
            for (int im = 0; im < 2; im++)
                LDSM4(a[im], sA + aBase[im] + ((kk * 32 + ahi) ^ aXor[im]));
            LDSM4(b, sB + bBase + ((kk * 32 + bhi) ^ bXor));
            #pragma unroll
            for (int im = 0; im < 2; im++)
                #pragma unroll
                for (int jn = 0; jn < 2; jn++)
                    mma_tf32(acc[im][jn], a[im], &b[jn * 2]);
        }
        __syncthreads();
    }

    float* se = smem_all;
    #pragma unroll
    for (int im = 0; im < 2; im++)
        #pragma unroll
        for (int jn = 0; jn < 2; jn++) {
            int r0 = wm * 32 + im * 16 + g;
            int c  = wn * 16 + jn * 8 + 2 * tig;
            se[r0 * EP2 + c]           = acc[im][jn][0];
            se[r0 * EP2 + c + 1]       = acc[im][jn][1];
            se[(r0 + 8) * EP2 + c]     = acc[im][jn][2];
            se[(r0 + 8) * EP2 + c + 1] = acc[im][jn][3];
        }
    __syncthreads();
    const float gam = *gamma_p;
    #pragma unroll
    for (int it = 0; it < 4; it++) {
        int id = tid + it * 128;
        int row = id >> 3, c4 = id & 7;
        float4 v = *(const float4*)(se + row * EP2 + c4 * 4);
        int rowg = bm * 64 + row;
        int cc4 = bn * 8 + c4;
        float4 p4 = ((const float4*)g_P)[(size_t)rowg * 256 + cc4];
        float4 b4 = ((const float4*)bbase)[cc4];
        float4 h4 = ((const float4*)hA)[(size_t)rowg * 256 + cc4];
        float4 x;
        x.x = h4.x + gam * (v.x + p4.x + b4.x);
        x.y = h4.y + gam * (v.y + p4.y + b4.y);
        x.z = h4.z + gam * (v.z + p4.z + b4.z);
        x.w = h4.w + gam * (v.w + p4.w + b4.w);
        ((float4*)g_X)[(size_t)rowg * 256 + cc4] = x;
        float s  = x.x + x.y + x.z + x.w;
        float ss = x.x * x.x + x.y * x.y + x.z * x.z + x.w * x.w;
        #pragma unroll
        for (int off = 4; off; off >>= 1) {
            s  += __shfl_xor_sync(0xffffffffu, s, off);
            ss += __shfl_xor_sync(0xffffffffu, ss, off);
        }
        if ((tid & 7) == 0) g_part[rowg * 32 + bn] = make_float2(s, ss);
    }
}

// ---------------- LayerNorm: warp per row, normalize-only ----------------
__global__ void __launch_bounds__(256) ln_kernel(const float* __restrict__ lns,
                                                 const float* __restrict__ lnb,
                                                 float* __restrict__ out) {
    const int tid = threadIdx.x;
    const int lane = tid & 31;
    const int row = blockIdx.x * 8 + (tid >> 5);
    float2 p = g_part[row * 32 + lane];
    float s = p.x, ss = p.y;
    #pragma unroll
    for (int off = 16; off; off >>= 1) {
        s  += __shfl_xor_sync(0xffffffffu, s, off);
        ss += __shfl_xor_sync(0xffffffffu, ss, off);
    }
    const float mean = s * (1.f / 1024.f);
    const float inv  = rsqrtf(ss * (1.f / 1024.f) - mean * mean + LN_EPS);
    #pragma unroll
    for (int j = 0; j < 8; j++) {
        int c4 = lane + j * 32;
        float4 x = ((const float4*)g_X)[(size_t)row * 256 + c4];
        float4 sc = ((const float4*)lns)[c4];
        float4 bi = ((const float4*)lnb)[c4];
        float4 o;
        o.x = (x.x - mean) * inv * sc.x + bi.x;
        o.y = (x.y - mean) * inv * sc.y + bi.y;
        o.z = (x.z - mean) * inv * sc.z + bi.z;
        o.w = (x.w - mean) * inv * sc.w + bi.w;
        ((float4*)out)[(size_t)row * 256 + c4] = o;
    }
}

// ---------------- launch: kernel launches ONLY, no host API calls ------------
extern "C" void kernel_launch(void* const* d_in, const int* in_sizes, int n_in,
                              void* d_out, int out_size) {
    const float* hA    = (const float*)d_in[0];
    const float* pool  = (const float*)d_in[1];
    const float* alpha = (const float*)d_in[2];
    const float* W     = (const float*)d_in[3];
    const float* bb    = (const float*)d_in[4];
    const float* gamma = (const float*)d_in[5];
    const float* lns   = (const float*)d_in[6];
    const float* lnb   = (const float*)d_in[7];
    float* out = (float*)d_out;

    k1_kernel<<<161, 128>>>(hA, W, pool, alpha);
    k2_kernel<<<128, 128>>>(hA, bb, gamma);
    ln_kernel<<<32, 256>>>(lns, lnb, out);
}

// round 6
// speedup vs baseline: 1.4555x; 1.1998x over previous
#include <cuda_runtime.h>
#include <cstdint>

#define D_A      1024
#define NEXP     64
#define BATCH    256
#define POOL_DIM 33792
#define U_END    16384
#define V_END    32768
#define KEXT     1088
#define LN_EPS   1e-5f

#define NK1 32            /* 1024/32 */
#define NK2 34            /* 1088/32 */
#define A_STG 8192        /* 64 rows x 128B */
#define B_STG1 8192       /* 64 rows x 128B */
#define B_STG2 4096       /* 32 rows x 128B */
#define EP1 72            /* epi stride floats */
#define EP2 40

// ---------------- scratch ----------------
__device__ __align__(128) float  g_BmatT[(size_t)1024 * KEXT];  // [c][k]
__device__ __align__(128) float  g_S[BATCH * KEXT];             // [b][k]
__device__ __align__(128) float  g_P[BATCH * 1024];
__device__ __align__(128) float  g_X[BATCH * 1024];
__device__ __align__(128) float2 g_part[BATCH * 32];            // [row][bn]

// ---------------- helpers ----------------
__device__ __forceinline__ uint32_t smem_u32(const void* p) {
    uint32_t a;
    asm("{ .reg .u64 t; cvta.to.shared.u64 t, %1; cvt.u32.u64 %0, t; }" : "=r"(a) : "l"(p));
    return a;
}
__device__ __forceinline__ uint32_t swz(uint32_t off) { return off ^ ((off >> 3) & 0x70); }
__device__ __forceinline__ void cpa16(uint32_t saddr, const void* g) {
    asm volatile("cp.async.cg.shared.global [%0], [%1], 16;\n" :: "r"(saddr), "l"(g));
}
__device__ __forceinline__ void cp_commit() { asm volatile("cp.async.commit_group;\n"); }
template<int N> __device__ __forceinline__ void cp_wait() {
    asm volatile("cp.async.wait_group %0;\n" :: "n"(N));
}
#define LDSM4(R, addr) \
    asm volatile("ldmatrix.sync.aligned.m8n8.x4.shared.b16 {%0,%1,%2,%3}, [%4];" \
        : "=r"((R)[0]), "=r"((R)[1]), "=r"((R)[2]), "=r"((R)[3]) : "r"(addr))
__device__ __forceinline__ void mma_tf32(float* c, const uint32_t* a, const uint32_t* b) {
    asm volatile(
        "mma.sync.aligned.m16n8k8.row.col.f32.tf32.tf32.f32 "
        "{%0,%1,%2,%3}, {%4,%5,%6,%7}, {%8,%9}, {%0,%1,%2,%3};\n"
        : "+f"(c[0]), "+f"(c[1]), "+f"(c[2]), "+f"(c[3])
        : "r"(a[0]), "r"(a[1]), "r"(a[2]), "r"(a[3]), "r"(b[0]), "r"(b[1]));
}

// ---------------- prep role (17 blocks x 128 threads) -----------------------
// pid 0..15: 64 c-rows each of g_BmatT; pid 16: alpha cols of g_S
__device__ void prep_role(int pid, float* sf, const float* __restrict__ pool,
                          const float* __restrict__ alpha) {
    const int tid = threadIdx.x;
    if (pid == 16) {
        #pragma unroll 8
        for (int it = 0; it < 128; it++) {
            int e = tid + it * 128;
            int b = e >> 6, n = e & 63;
            g_S[(size_t)b * KEXT + 1024 + n] = alpha[b * NEXP + n];
        }
        return;
    }
    for (int half = 0; half < 2; half++) {
        const int c0 = pid * 64 + half * 32;
        for (int ng = 0; ng < 4; ng++) {
            #pragma unroll
            for (int it = 0; it < 16; it++) {
                int e = tid + it * 128;
                int nl = e >> 7, i4 = e & 127;
                const float4* src = (const float4*)(pool + (size_t)(ng * 16 + nl) * POOL_DIM + c0 * 16) + i4;
                *(float4*)(sf + nl * 528 + i4 * 4) = *src;
            }
            __syncthreads();
            #pragma unroll 8
            for (int it = 0; it < 64; it++) {
                int e = tid + it * 128;
                int cl = e >> 8, j = e & 255;
                int nl = j >> 4, r = j & 15;
                g_BmatT[(size_t)(c0 + cl) * KEXT + ng * 256 + j] = sf[nl * 528 + cl * 16 + r];
            }
            __syncthreads();
        }
        #pragma unroll
        for (int it = 0; it < 16; it++) {
            int e = tid + it * 128;
            int n = e >> 5, cl = e & 31;
            sf[n * 33 + cl] = pool[(size_t)n * POOL_DIM + V_END + c0 + cl];
        }
        __syncthreads();
        #pragma unroll
        for (int it = 0; it < 16; it++) {
            int e = tid + it * 128;
            int cl = e >> 6, n = e & 63;
            g_BmatT[(size_t)(c0 + cl) * KEXT + 1024 + n] = sf[n * 33 + cl];
        }
        __syncthreads();
    }
}

// ---------------- k1: blocks 0..16 prep; 17..144 GEMM1 (64x64 tiles) --------
// C[256,2048] = h_A * [W_base | V]^T ; cols<1024 -> g_P, cols>=1024 -> g_S*alpha
__global__ void __launch_bounds__(128) k1_kernel(const float* __restrict__ hA,
                                                 const float* __restrict__ W,
                                                 const float* __restrict__ pool,
                                                 const float* __restrict__ alpha) {
    __shared__ __align__(128) float smem_all[12288];   // 49152 B static (3 stages)
    const int bid = blockIdx.x;
    if (bid < 17) { prep_role(bid, smem_all, pool, alpha); return; }

    const uint32_t sb = smem_u32(smem_all);
    const int gb = bid - 17;
    const int bm = gb >> 5;           // 0..3
    const int bn = gb & 31;           // 0..31
    const int tid = threadIdx.x;
    const int lane = tid & 31, warp = tid >> 5;
    const int wm = warp & 1, wn = warp >> 1;
    const int g = lane >> 2, tig = lane & 3;

    const uint32_t sbA = sb;                  // 3 stages x 8192
    const uint32_t sbB = sb + 3 * A_STG;      // 3 stages x 8192

    // cp.async maps (4 chunks each side per thread)
    const float* aPtr[4]; uint32_t aDst[4];
    const float* bPtr[4]; uint32_t bDst[4];
    #pragma unroll
    for (int q = 0; q < 4; q++) {
        int id = tid + q * 128;
        int row = id >> 3, c8 = id & 7;
        aPtr[q] = hA + (size_t)(bm * 64 + row) * D_A + c8 * 4;
        aDst[q] = swz(row * 128 + c8 * 16);
        int j = bn * 64 + row;
        const float* base = (bn < 16)
            ? (W + (size_t)j * D_A)
            : (pool + (size_t)((j - 1024) >> 4) * POOL_DIM + U_END + (size_t)((j - 1024) & 15) * D_A);
        bPtr[q] = base + c8 * 4;
        bDst[q] = swz(row * 128 + c8 * 16);
    }
    auto fill = [&](int s, int kc) {
        const int off = kc * 32;
        #pragma unroll
        for (int q = 0; q < 4; q++) {
            cpa16(sbA + s * A_STG + aDst[q], aPtr[q] + off);
            cpa16(sbB + s * B_STG1 + bDst[q], bPtr[q] + off);
        }
    };

    // ldmatrix address precompute
    uint32_t aBase[2], aXor[2], bBase[2], bXor[2];
    const uint32_t ahi = ((lane >> 4) & 1) * 16;
    const uint32_t bhi = ((lane >> 3) & 1) * 16;
    #pragma unroll
    for (int im = 0; im < 2; im++) {
        int r = wm * 32 + im * 16 + (lane & 7) + ((lane >> 3) & 1) * 8;
        aBase[im] = r * 128; aXor[im] = (r & 7) << 4;
    }
    #pragma unroll
    for (int jp = 0; jp < 2; jp++) {
        int r = wn * 32 + jp * 16 + (lane & 7) + ((lane >> 4) & 1) * 8;
        bBase[jp] = r * 128; bXor[jp] = (r & 7) << 4;
    }

    float acc[2][4][4];
    #pragma unroll
    for (int i = 0; i < 2; i++)
        #pragma unroll
        for (int j = 0; j < 4; j++)
            #pragma unroll
            for (int e = 0; e < 4; e++) acc[i][j][e] = 0.f;

    fill(0, 0); cp_commit(); fill(1, 1); cp_commit();

    int s = 0, sw = 2;                       // compute stage / fill stage
    for (int i = 0; i < NK1; i++) {
        cp_wait<1>();
        __syncthreads();
        const uint32_t sA = sbA + s * A_STG;
        const uint32_t sB = sbB + s * B_STG1;
        #pragma unroll
        for (int kk = 0; kk < 4; kk++) {
            uint32_t a[2][4], b[2][4];
            #pragma unroll
            for (int im = 0; im < 2; im++)
                LDSM4(a[im], sA + aBase[im] + ((kk * 32 + ahi) ^ aXor[im]));
            #pragma unroll
            for (int jp = 0; jp < 2; jp++)
                LDSM4(b[jp], sB + bBase[jp] + ((kk * 32 + bhi) ^ bXor[jp]));
            #pragma unroll
            for (int im = 0; im < 2; im++)
                #pragma unroll
                for (int jn = 0; jn < 4; jn++)
                    mma_tf32(acc[im][jn], a[im], &b[jn >> 1][(jn & 1) * 2]);
        }
        if (i + 2 < NK1) fill(sw, i + 2);
        cp_commit();                          // one commit per iter (may be empty)
        s = (s == 2) ? 0 : s + 1;
        sw = (sw == 2) ? 0 : sw + 1;
    }
    __syncthreads();

    // stage accumulators through smem, then coalesced float4 out
    float* se = smem_all;
    #pragma unroll
    for (int im = 0; im < 2; im++)
        #pragma unroll
        for (int jn = 0; jn < 4; jn++) {
            int r0 = wm * 32 + im * 16 + g;
            int c  = wn * 32 + jn * 8 + 2 * tig;
            se[r0 * EP1 + c]           = acc[im][jn][0];
            se[r0 * EP1 + c + 1]       = acc[im][jn][1];
            se[(r0 + 8) * EP1 + c]     = acc[im][jn][2];
            se[(r0 + 8) * EP1 + c + 1] = acc[im][jn][3];
        }
    __syncthreads();
    #pragma unroll
    for (int it = 0; it < 8; it++) {
        int id = tid + it * 128;
        int row = id >> 4, c4 = id & 15;
        float4 v = *(const float4*)(se + row * EP1 + c4 * 4);
        int rowg = bm * 64 + row;
        if (bn < 16) {
            ((float4*)g_P)[(size_t)rowg * 256 + bn * 16 + c4] = v;
        } else {
            int n = (bn - 16) * 4 + (c4 >> 2);
            float a = alpha[rowg * NEXP + n];
            v.x *= a; v.y *= a; v.z *= a; v.w *= a;
            ((float4*)g_S)[(size_t)rowg * 272 + (bn - 16) * 16 + c4] = v;
        }
    }
}

// ---------------- k2: GEMM2 64x32 tiles; X = hA + gamma*(S@BmatT^T + P + b) --
__global__ void __launch_bounds__(128) k2_kernel(const float* __restrict__ hA,
                                                 const float* __restrict__ bbase,
                                                 const float* __restrict__ gamma_p) {
    __shared__ __align__(128) float smem_all[9216];   // 36864 B (3 stages)
    const uint32_t sb = smem_u32(smem_all);
    const int bid = blockIdx.x;
    const int bm = bid >> 5;          // 0..3
    const int bn = bid & 31;          // 0..31
    const int tid = threadIdx.x;
    const int lane = tid & 31, warp = tid >> 5;
    const int wm = warp & 1, wn = warp >> 1;
    const int g = lane >> 2, tig = lane & 3;

    const uint32_t sbA = sb;                  // 3 stages x 8192
    const uint32_t sbB = sb + 3 * A_STG;      // 3 stages x 4096

    const float* aPtr[4]; uint32_t aDst[4];
    #pragma unroll
    for (int q = 0; q < 4; q++) {
        int id = tid + q * 128;
        int row = id >> 3, c8 = id & 7;
        aPtr[q] = g_S + (size_t)(bm * 64 + row) * KEXT + c8 * 4;
        aDst[q] = swz(row * 128 + c8 * 16);
    }
    const float* bPtr[2]; uint32_t bDst[2];
    #pragma unroll
    for (int q = 0; q < 2; q++) {
        int id = tid + q * 128;
        int row = id >> 3, c8 = id & 7;
        bPtr[q] = g_BmatT + (size_t)(bn * 32 + row) * KEXT + c8 * 4;
        bDst[q] = swz(row * 128 + c8 * 16);
    }
    auto fill = [&](int s, int kc) {
        const int off = kc * 32;
        #pragma unroll
        for (int q = 0; q < 4; q++)
            cpa16(sbA + s * A_STG + aDst[q], aPtr[q] + off);
        #pragma unroll
        for (int q = 0; q < 2; q++)
            cpa16(sbB + s * B_STG2 + bDst[q], bPtr[q] + off);
    };

    uint32_t aBase[2], aXor[2], bBase, bXor;
    const uint32_t ahi = ((lane >> 4) & 1) * 16;
    const uint32_t bhi = ((lane >> 3) & 1) * 16;
    #pragma unroll
    for (int im = 0; im < 2; im++) {
        int r = wm * 32 + im * 16 + (lane & 7) + ((lane >> 3) & 1) * 8;
        aBase[im] = r * 128; aXor[im] = (r & 7) << 4;
    }
    {
        int r = wn * 16 + (lane & 7) + ((lane >> 4) & 1) * 8;
        bBase = r * 128; bXor = (r & 7) << 4;
    }

    float acc[2][2][4];
    #pragma unroll
    for (int i = 0; i < 2; i++)
        #pragma unroll
        for (int j = 0; j < 2; j++)
            #pragma unroll
            for (int e = 0; e < 4; e++) acc[i][j][e] = 0.f;

    fill(0, 0); cp_commit(); fill(1, 1); cp_commit();

    int s = 0, sw = 2;
    for (int i = 0; i < NK2; i++) {
        cp_wait<1>();
        __syncthreads();
        const uint32_t sA = sbA + s * A_STG;
        const uint32_t sB = sbB + s * B_STG2;
        #pragma unroll
        for (int kk = 0; kk < 4; kk++) {
            uint32_t a[2][4], b[4];
            #pragma unroll
            for (int im = 0; im < 2; im++)
                LDSM4(a[im], sA + aBase[im] + ((kk * 32 + ahi) ^ aXor[im]));
            LDSM4(b, sB + bBase + ((kk * 32 + bhi) ^ bXor));
            #pragma unroll
            for (int im = 0; im < 2; im++)
                #pragma unroll
                for (int jn = 0; jn < 2; jn++)
                    mma_tf32(acc[im][jn], a[im], &b[jn * 2]);
        }
        if (i + 2 < NK2) fill(sw, i + 2);
        cp_commit();
        s = (s == 2) ? 0 : s + 1;
        sw = (sw == 2) ? 0 : sw + 1;
    }
    __syncthreads();

    float* se = smem_all;
    #pragma unroll
    for (int im = 0; im < 2; im++)
        #pragma unroll
        for (int jn = 0; jn < 2; jn++) {
            int r0 = wm * 32 + im * 16 + g;
            int c  = wn * 16 + jn * 8 + 2 * tig;
            se[r0 * EP2 + c]           = acc[im][jn][0];
            se[r0 * EP2 + c + 1]       = acc[im][jn][1];
            se[(r0 + 8) * EP2 + c]     = acc[im][jn][2];
            se[(r0 + 8) * EP2 + c + 1] = acc[im][jn][3];
        }
    __syncthreads();
    const float gam = *gamma_p;
    #pragma unroll
    for (int it = 0; it < 4; it++) {
        int id = tid + it * 128;
        int row = id >> 3, c4 = id & 7;
        float4 v = *(const float4*)(se + row * EP2 + c4 * 4);
        int rowg = bm * 64 + row;
        int cc4 = bn * 8 + c4;
        float4 p4 = ((const float4*)g_P)[(size_t)rowg * 256 + cc4];
        float4 b4 = ((const float4*)bbase)[cc4];
        float4 h4 = ((const float4*)hA)[(size_t)rowg * 256 + cc4];
        float4 x;
        x.x = h4.x + gam * (v.x + p4.x + b4.x);
        x.y = h4.y + gam * (v.y + p4.y + b4.y);
        x.z = h4.z + gam * (v.z + p4.z + b4.z);
        x.w = h4.w + gam * (v.w + p4.w + b4.w);
        ((float4*)g_X)[(size_t)rowg * 256 + cc4] = x;
        float s2  = x.x + x.y + x.z + x.w;
        float ss2 = x.x * x.x + x.y * x.y + x.z * x.z + x.w * x.w;
        #pragma unroll
        for (int off = 4; off; off >>= 1) {
            s2  += __shfl_xor_sync(0xffffffffu, s2, off);
            ss2 += __shfl_xor_sync(0xffffffffu, ss2, off);
        }
        if ((tid & 7) == 0) g_part[rowg * 32 + bn] = make_float2(s2, ss2);
    }
}

// ---------------- LayerNorm: warp per row, normalize-only ----------------
__global__ void __launch_bounds__(256) ln_kernel(const float* __restrict__ lns,
                                                 const float* __restrict__ lnb,
                                                 float* __restrict__ out) {
    const int tid = threadIdx.x;
    const int lane = tid & 31;
    const int row = blockIdx.x * 8 + (tid >> 5);
    float2 p = g_part[row * 32 + lane];
    float s = p.x, ss = p.y;
    #pragma unroll
    for (int off = 16; off; off >>= 1) {
        s  += __shfl_xor_sync(0xffffffffu, s, off);
        ss += __shfl_xor_sync(0xffffffffu, ss, off);
    }
    const float mean = s * (1.f / 1024.f);
    const float inv  = rsqrtf(ss * (1.f / 1024.f) - mean * mean + LN_EPS);
    #pragma unroll
    for (int j = 0; j < 8; j++) {
        int c4 = lane + j * 32;
        float4 x = ((const float4*)g_X)[(size_t)row * 256 + c4];
        float4 sc = ((const float4*)lns)[c4];
        float4 bi = ((const float4*)lnb)[c4];
        float4 o;
        o.x = (x.x - mean) * inv * sc.x + bi.x;
        o.y = (x.y - mean) * inv * sc.y + bi.y;
        o.z = (x.z - mean) * inv * sc.z + bi.z;
        o.w = (x.w - mean) * inv * sc.w + bi.w;
        ((float4*)out)[(size_t)row * 256 + c4] = o;
    }
}

// ---------------- launch: kernel launches ONLY ----------------
extern "C" void kernel_launch(void* const* d_in, const int* in_sizes, int n_in,
                              void* d_out, int out_size) {
    const float* hA    = (const float*)d_in[0];
    const float* pool  = (const float*)d_in[1];
    const float* alpha = (const float*)d_in[2];
    const float* W     = (const float*)d_in[3];
    const float* bb    = (const float*)d_in[4];
    const float* gamma = (const float*)d_in[5];
    const float* lns   = (const float*)d_in[6];
    const float* lnb   = (const float*)d_in[7];
    float* out = (float*)d_out;

    k1_kernel<<<145, 128>>>(hA, W, pool, alpha);
    k2_kernel<<<128, 128>>>(hA, bb, gamma);
    ln_kernel<<<32, 256>>>(lns, lnb, out);
}

// round 7
// speedup vs baseline: 1.4995x; 1.0302x over previous
#include <cuda_runtime.h>
#include <cstdint>

#define D_A      1024
#define NEXP     64
#define BATCH    256
#define POOL_DIM 33792
#define U_END    16384
#define V_END    32768
#define KEXT     1088
#define LN_EPS   1e-5f

#define NK1 32            /* 1024/32 */
#define NK2 34            /* 1088/32 */
#define A_STG 8192        /* 64 rows x 128B */
#define B_STG1 8192       /* 64 rows x 128B */
#define B_STG2 4096       /* 32 rows x 128B */
#define EP1 68            /* k1 epi stride floats (64 + 4 pad) */
#define EP2 36            /* k2 epi stride floats (32 + 4 pad) */

// ---------------- scratch ----------------
__device__ __align__(128) float  g_BmatT[(size_t)1024 * KEXT];  // [c][k]
__device__ __align__(128) float  g_S[BATCH * KEXT];             // [b][k]
__device__ __align__(128) float  g_P[BATCH * 1024];
__device__ __align__(128) float  g_X[BATCH * 1024];
__device__ __align__(128) float2 g_part[BATCH * 32];            // [row][bn]

// ---------------- helpers ----------------
__device__ __forceinline__ uint32_t smem_u32(const void* p) {
    uint32_t a;
    asm("{ .reg .u64 t; cvta.to.shared.u64 t, %1; cvt.u32.u64 %0, t; }" : "=r"(a) : "l"(p));
    return a;
}
__device__ __forceinline__ uint32_t swz(uint32_t off) { return off ^ ((off >> 3) & 0x70); }
__device__ __forceinline__ void cpa16(uint32_t saddr, const void* g) {
    asm volatile("cp.async.cg.shared.global [%0], [%1], 16;\n" :: "r"(saddr), "l"(g));
}
__device__ __forceinline__ void cp_commit() { asm volatile("cp.async.commit_group;\n"); }
template<int N> __device__ __forceinline__ void cp_wait() {
    asm volatile("cp.async.wait_group %0;\n" :: "n"(N));
}
#define LDSM4(R, addr) \
    asm volatile("ldmatrix.sync.aligned.m8n8.x4.shared.b16 {%0,%1,%2,%3}, [%4];" \
        : "=r"((R)[0]), "=r"((R)[1]), "=r"((R)[2]), "=r"((R)[3]) : "r"(addr))
__device__ __forceinline__ void mma_tf32(float* c, const uint32_t* a, const uint32_t* b) {
    asm volatile(
        "mma.sync.aligned.m16n8k8.row.col.f32.tf32.tf32.f32 "
        "{%0,%1,%2,%3}, {%4,%5,%6,%7}, {%8,%9}, {%0,%1,%2,%3};\n"
        : "+f"(c[0]), "+f"(c[1]), "+f"(c[2]), "+f"(c[3])
        : "r"(a[0]), "r"(a[1]), "r"(a[2]), "r"(a[3]), "r"(b[0]), "r"(b[1]));
}

// ---------------- prep role (17 blocks x 256 threads) -----------------------
// pid 0..15: 64 c-rows each of g_BmatT; pid 16: alpha cols of g_S
__device__ void prep_role(int pid, float* sf, const float* __restrict__ pool,
                          const float* __restrict__ alpha) {
    const int tid = threadIdx.x;
    if (pid == 16) {
        #pragma unroll 8
        for (int it = 0; it < 64; it++) {
            int e = tid + it * 256;
            int b = e >> 6, n = e & 63;
            g_S[(size_t)b * KEXT + 1024 + n] = alpha[b * NEXP + n];
        }
        return;
    }
    for (int half = 0; half < 2; half++) {
        const int c0 = pid * 64 + half * 32;
        for (int ng = 0; ng < 4; ng++) {
            #pragma unroll
            for (int it = 0; it < 8; it++) {
                int e = tid + it * 256;
                int nl = e >> 7, i4 = e & 127;
                const float4* src = (const float4*)(pool + (size_t)(ng * 16 + nl) * POOL_DIM + c0 * 16) + i4;
                *(float4*)(sf + nl * 528 + i4 * 4) = *src;
            }
            __syncthreads();
            #pragma unroll 8
            for (int it = 0; it < 32; it++) {
                int e = tid + it * 256;
                int cl = e >> 8, j = e & 255;
                int nl = j >> 4, r = j & 15;
                g_BmatT[(size_t)(c0 + cl) * KEXT + ng * 256 + j] = sf[nl * 528 + cl * 16 + r];
            }
            __syncthreads();
        }
        #pragma unroll
        for (int it = 0; it < 8; it++) {
            int e = tid + it * 256;
            int n = e >> 5, cl = e & 31;
            sf[n * 33 + cl] = pool[(size_t)n * POOL_DIM + V_END + c0 + cl];
        }
        __syncthreads();
        #pragma unroll
        for (int it = 0; it < 8; it++) {
            int e = tid + it * 256;
            int cl = e >> 6, n = e & 63;
            g_BmatT[(size_t)(c0 + cl) * KEXT + 1024 + n] = sf[n * 33 + cl];
        }
        __syncthreads();
    }
}

// ---------------- k1: blocks 0..16 prep; 17..144 GEMM1 (64x64, 8 warps) -----
// C[256,2048] = h_A * [W_base | V]^T ; cols<1024 -> g_P, cols>=1024 -> g_S*alpha
__global__ void __launch_bounds__(256) k1_kernel(const float* __restrict__ hA,
                                                 const float* __restrict__ W,
                                                 const float* __restrict__ pool,
                                                 const float* __restrict__ alpha) {
    __shared__ __align__(128) float smem_all[12288];   // 49152 B static (3 stages)
    const int bid = blockIdx.x;
    if (bid < 17) { prep_role(bid, smem_all, pool, alpha); return; }

    const uint32_t sb = smem_u32(smem_all);
    const int gb = bid - 17;
    const int bm = gb >> 5;           // 0..3
    const int bn = gb & 31;           // 0..31
    const int tid = threadIdx.x;
    const int lane = tid & 31, warp = tid >> 5;
    const int wm = warp & 1;          // 2 row groups of 32
    const int wn = warp >> 1;         // 4 col groups of 16
    const int g = lane >> 2, tig = lane & 3;

    const uint32_t sbA = sb;                  // 3 stages x 8192
    const uint32_t sbB = sb + 3 * A_STG;      // 3 stages x 8192

    // cp.async maps (2 chunks each side per thread; 256 threads)
    const float* aPtr[2]; uint32_t aDst[2];
    const float* bPtr[2]; uint32_t bDst[2];
    #pragma unroll
    for (int q = 0; q < 2; q++) {
        int id = tid + q * 256;
        int row = id >> 3, c8 = id & 7;
        aPtr[q] = hA + (size_t)(bm * 64 + row) * D_A + c8 * 4;
        aDst[q] = swz(row * 128 + c8 * 16);
        int j = bn * 64 + row;
        const float* base = (bn < 16)
            ? (W + (size_t)j * D_A)
            : (pool + (size_t)((j - 1024) >> 4) * POOL_DIM + U_END + (size_t)((j - 1024) & 15) * D_A);
        bPtr[q] = base + c8 * 4;
        bDst[q] = swz(row * 128 + c8 * 16);
    }
    auto fill = [&](int s, int kc) {
        const int off = kc * 32;
        #pragma unroll
        for (int q = 0; q < 2; q++) {
            cpa16(sbA + s * A_STG + aDst[q], aPtr[q] + off);
            cpa16(sbB + s * B_STG1 + bDst[q], bPtr[q] + off);
        }
    };

    // ldmatrix addresses: A m32 (2 frags), B n16 (1 frag)
    uint32_t aBase[2], aXor[2], bBase, bXor;
    const uint32_t ahi = ((lane >> 4) & 1) * 16;
    const uint32_t bhi = ((lane >> 3) & 1) * 16;
    #pragma unroll
    for (int im = 0; im < 2; im++) {
        int r = wm * 32 + im * 16 + (lane & 7) + ((lane >> 3) & 1) * 8;
        aBase[im] = r * 128; aXor[im] = (r & 7) << 4;
    }
    {
        int r = wn * 16 + (lane & 7) + ((lane >> 4) & 1) * 8;
        bBase = r * 128; bXor = (r & 7) << 4;
    }

    float acc[2][2][4];
    #pragma unroll
    for (int i = 0; i < 2; i++)
        #pragma unroll
        for (int j = 0; j < 2; j++)
            #pragma unroll
            for (int e = 0; e < 4; e++) acc[i][j][e] = 0.f;

    fill(0, 0); cp_commit(); fill(1, 1); cp_commit();

    int s = 0, sw = 2;
    for (int i = 0; i < NK1; i++) {
        cp_wait<1>();
        __syncthreads();
        if (i + 2 < NK1) fill(sw, i + 2);   // early prefetch, before compute
        cp_commit();
        const uint32_t sA = sbA + s * A_STG;
        const uint32_t sB = sbB + s * B_STG1;
        #pragma unroll
        for (int kk = 0; kk < 4; kk++) {
            uint32_t a[2][4], b[4];
            #pragma unroll
            for (int im = 0; im < 2; im++)
                LDSM4(a[im], sA + aBase[im] + ((kk * 32 + ahi) ^ aXor[im]));
            LDSM4(b, sB + bBase + ((kk * 32 + bhi) ^ bXor));
            #pragma unroll
            for (int im = 0; im < 2; im++)
                #pragma unroll
                for (int jn = 0; jn < 2; jn++)
                    mma_tf32(acc[im][jn], a[im], &b[jn * 2]);
        }
        s = (s == 2) ? 0 : s + 1;
        sw = (sw == 2) ? 0 : sw + 1;
    }
    __syncthreads();

    // stage accumulators through smem, then coalesced float4 out
    float* se = smem_all;
    #pragma unroll
    for (int im = 0; im < 2; im++)
        #pragma unroll
        for (int jn = 0; jn < 2; jn++) {
            int r0 = wm * 32 + im * 16 + g;
            int c  = wn * 16 + jn * 8 + 2 * tig;
            se[r0 * EP1 + c]           = acc[im][jn][0];
            se[r0 * EP1 + c + 1]       = acc[im][jn][1];
            se[(r0 + 8) * EP1 + c]     = acc[im][jn][2];
            se[(r0 + 8) * EP1 + c + 1] = acc[im][jn][3];
        }
    __syncthreads();
    #pragma unroll
    for (int it = 0; it < 4; it++) {
        int id = tid + it * 256;
        int row = id >> 4, c4 = id & 15;
        float4 v = *(const float4*)(se + row * EP1 + c4 * 4);
        int rowg = bm * 64 + row;
        if (bn < 16) {
            ((float4*)g_P)[(size_t)rowg * 256 + bn * 16 + c4] = v;
        } else {
            int n = (bn - 16) * 4 + (c4 >> 2);
            float a = alpha[rowg * NEXP + n];
            v.x *= a; v.y *= a; v.z *= a; v.w *= a;
            ((float4*)g_S)[(size_t)rowg * 272 + (bn - 16) * 16 + c4] = v;
        }
    }
}

// ---------------- k2: GEMM2 64x32, 8 warps, 4 stages -------------------------
// X = hA + gamma*(S@BmatT^T + P + b_base)
__global__ void __launch_bounds__(256) k2_kernel(const float* __restrict__ hA,
                                                 const float* __restrict__ bbase,
                                                 const float* __restrict__ gamma_p) {
    __shared__ __align__(128) float smem_all[12288];   // 49152 B (4 stages x 12KB)
    const uint32_t sb = smem_u32(smem_all);
    const int bid = blockIdx.x;
    const int bm = bid >> 5;          // 0..3
    const int bn = bid & 31;          // 0..31
    const int tid = threadIdx.x;
    const int lane = tid & 31, warp = tid >> 5;
    const int wm = warp & 3;          // 4 row groups of 16
    const int wn = warp >> 2;         // 2 col groups of 16
    const int g = lane >> 2, tig = lane & 3;

    const uint32_t sbA = sb;                  // 4 stages x 8192
    const uint32_t sbB = sb + 4 * A_STG;      // 4 stages x 4096

    const float* aPtr[2]; uint32_t aDst[2];
    #pragma unroll
    for (int q = 0; q < 2; q++) {
        int id = tid + q * 256;
        int row = id >> 3, c8 = id & 7;
        aPtr[q] = g_S + (size_t)(bm * 64 + row) * KEXT + c8 * 4;
        aDst[q] = swz(row * 128 + c8 * 16);
    }
    const float* bPtr; uint32_t bDst;
    {
        int row = tid >> 3, c8 = tid & 7;
        bPtr = g_BmatT + (size_t)(bn * 32 + row) * KEXT + c8 * 4;
        bDst = swz(row * 128 + c8 * 16);
    }
    auto fill = [&](int s, int kc) {
        const int off = kc * 32;
        #pragma unroll
        for (int q = 0; q < 2; q++)
            cpa16(sbA + s * A_STG + aDst[q], aPtr[q] + off);
        cpa16(sbB + s * B_STG2 + bDst, bPtr + off);
    };

    uint32_t aBase, aXor, bBase, bXor;
    const uint32_t ahi = ((lane >> 4) & 1) * 16;
    const uint32_t bhi = ((lane >> 3) & 1) * 16;
    {
        int r = wm * 16 + (lane & 7) + ((lane >> 3) & 1) * 8;
        aBase = r * 128; aXor = (r & 7) << 4;
    }
    {
        int r = wn * 16 + (lane & 7) + ((lane >> 4) & 1) * 8;
        bBase = r * 128; bXor = (r & 7) << 4;
    }

    float acc[2][4];
    #pragma unroll
    for (int j = 0; j < 2; j++)
        #pragma unroll
        for (int e = 0; e < 4; e++) acc[j][e] = 0.f;

    fill(0, 0); cp_commit(); fill(1, 1); cp_commit(); fill(2, 2); cp_commit();

    for (int i = 0; i < NK2; i++) {
        cp_wait<2>();
        __syncthreads();
        if (i + 3 < NK2) fill((i + 3) & 3, i + 3);
        cp_commit();
        const int s = i & 3;
        const uint32_t sA = sbA + s * A_STG;
        const uint32_t sB = sbB + s * B_STG2;
        #pragma unroll
        for (int kk = 0; kk < 4; kk++) {
            uint32_t a[4], b[4];
            LDSM4(a, sA + aBase + ((kk * 32 + ahi) ^ aXor));
            LDSM4(b, sB + bBase + ((kk * 32 + bhi) ^ bXor));
            #pragma unroll
            for (int jn = 0; jn < 2; jn++)
                mma_tf32(acc[jn], a, &b[jn * 2]);
        }
    }
    __syncthreads();

    float* se = smem_all;
    #pragma unroll
    for (int jn = 0; jn < 2; jn++) {
        int r0 = wm * 16 + g;
        int c  = wn * 16 + jn * 8 + 2 * tig;
        se[r0 * EP2 + c]           = acc[jn][0];
        se[r0 * EP2 + c + 1]       = acc[jn][1];
        se[(r0 + 8) * EP2 + c]     = acc[jn][2];
        se[(r0 + 8) * EP2 + c + 1] = acc[jn][3];
    }
    __syncthreads();
    const float gam = *gamma_p;
    #pragma unroll
    for (int it = 0; it < 2; it++) {
        int id = tid + it * 256;
        int row = id >> 3, c4 = id & 7;
        float4 v = *(const float4*)(se + row * EP2 + c4 * 4);
        int rowg = bm * 64 + row;
        int cc4 = bn * 8 + c4;
        float4 p4 = ((const float4*)g_P)[(size_t)rowg * 256 + cc4];
        float4 b4 = ((const float4*)bbase)[cc4];
        float4 h4 = ((const float4*)hA)[(size_t)rowg * 256 + cc4];
        float4 x;
        x.x = h4.x + gam * (v.x + p4.x + b4.x);
        x.y = h4.y + gam * (v.y + p4.y + b4.y);
        x.z = h4.z + gam * (v.z + p4.z + b4.z);
        x.w = h4.w + gam * (v.w + p4.w + b4.w);
        ((float4*)g_X)[(size_t)rowg * 256 + cc4] = x;
        float s2  = x.x + x.y + x.z + x.w;
        float ss2 = x.x * x.x + x.y * x.y + x.z * x.z + x.w * x.w;
        #pragma unroll
        for (int off = 4; off; off >>= 1) {
            s2  += __shfl_xor_sync(0xffffffffu, s2, off);
            ss2 += __shfl_xor_sync(0xffffffffu, ss2, off);
        }
        if ((tid & 7) == 0) g_part[rowg * 32 + bn] = make_float2(s2, ss2);
    }
}

// ---------------- LayerNorm: warp per row, normalize-only ----------------
__global__ void __launch_bounds__(256) ln_kernel(const float* __restrict__ lns,
                                                 const float* __restrict__ lnb,
                                                 float* __restrict__ out) {
    const int tid = threadIdx.x;
    const int lane = tid & 31;
    const int row = blockIdx.x * 8 + (tid >> 5);
    float2 p = g_part[row * 32 + lane];
    float s = p.x, ss = p.y;
    #pragma unroll
    for (int off = 16; off; off >>= 1) {
        s  += __shfl_xor_sync(0xffffffffu, s, off);
        ss += __shfl_xor_sync(0xffffffffu, ss, off);
    }
    const float mean = s * (1.f / 1024.f);
    const float inv  = rsqrtf(ss * (1.f / 1024.f) - mean * mean + LN_EPS);
    #pragma unroll
    for (int j = 0; j < 8; j++) {
        int c4 = lane + j * 32;
        float4 x = ((const float4*)g_X)[(size_t)row * 256 + c4];
        float4 sc = ((const float4*)lns)[c4];
        float4 bi = ((const float4*)lnb)[c4];
        float4 o;
        o.x = (x.x - mean) * inv * sc.x + bi.x;
        o.y = (x.y - mean) * inv * sc.y + bi.y;
        o.z = (x.z - mean) * inv * sc.z + bi.z;
        o.w = (x.w - mean) * inv * sc.w + bi.w;
        ((float4*)out)[(size_t)row * 256 + c4] = o;
    }
}

// ---------------- launch: kernel launches ONLY ----------------
extern "C" void kernel_launch(void* const* d_in, const int* in_sizes, int n_in,
                              void* d_out, int out_size) {
    const float* hA    = (const float*)d_in[0];
    const float* pool  = (const float*)d_in[1];
    const float* alpha = (const float*)d_in[2];
    const float* W     = (const float*)d_in[3];
    const float* bb    = (const float*)d_in[4];
    const float* gamma = (const float*)d_in[5];
    const float* lns   = (const float*)d_in[6];
    const float* lnb   = (const float*)d_in[7];
    float* out = (float*)d_out;

    k1_kernel<<<145, 256>>>(hA, W, pool, alpha);
    k2_kernel<<<128, 256>>>(hA, bb, gamma);
    ln_kernel<<<32, 256>>>(lns, lnb, out);
}

// round 8
// speedup vs baseline: 1.5994x; 1.0666x over previous
#include <cuda_runtime.h>
#include <cstdint>

#define D_A      1024
#define NEXP     64
#define BATCH    256
#define POOL_DIM 33792
#define U_END    16384
#define V_END    32768
#define KEXT     1088
#define LN_EPS   1e-5f

#define NK1 32            /* 1024/32 */
#define NK2 34            /* 1088/32 */
#define A_STG 8192        /* 64 rows x 128B */
#define B_STG1 8192       /* 64 rows x 128B */
#define B_STG2 4096       /* 32 rows x 128B */
#define EP1 68            /* k1 epi stride floats (64 + 4 pad) */
#define EP2 36            /* k2 epi stride floats (32 + 4 pad) */

// ---------------- scratch ----------------
__device__ __align__(128) float  g_BmatT[(size_t)1024 * KEXT];  // [c][k]
__device__ __align__(128) float  g_S[BATCH * KEXT];             // [b][k]
__device__ __align__(128) float  g_P[BATCH * 1024];
__device__ __align__(128) float  g_X[BATCH * 1024];
__device__ __align__(128) float2 g_part[BATCH * 32];            // [row][bn]

// ---------------- helpers ----------------
__device__ __forceinline__ uint32_t smem_u32(const void* p) {
    uint32_t a;
    asm("{ .reg .u64 t; cvta.to.shared.u64 t, %1; cvt.u32.u64 %0, t; }" : "=r"(a) : "l"(p));
    return a;
}
__device__ __forceinline__ uint32_t swz(uint32_t off) { return off ^ ((off >> 3) & 0x70); }
__device__ __forceinline__ void cpa16(uint32_t saddr, const void* g) {
    asm volatile("cp.async.cg.shared.global [%0], [%1], 16;\n" :: "r"(saddr), "l"(g));
}
__device__ __forceinline__ void cp_commit() { asm volatile("cp.async.commit_group;\n"); }
template<int N> __device__ __forceinline__ void cp_wait() {
    asm volatile("cp.async.wait_group %0;\n" :: "n"(N));
}
#define LDSM4(R, addr) \
    asm volatile("ldmatrix.sync.aligned.m8n8.x4.shared.b16 {%0,%1,%2,%3}, [%4];" \
        : "=r"((R)[0]), "=r"((R)[1]), "=r"((R)[2]), "=r"((R)[3]) : "r"(addr))
__device__ __forceinline__ void mma_tf32(float* c, const uint32_t* a, const uint32_t* b) {
    asm volatile(
        "mma.sync.aligned.m16n8k8.row.col.f32.tf32.tf32.f32 "
        "{%0,%1,%2,%3}, {%4,%5,%6,%7}, {%8,%9}, {%0,%1,%2,%3};\n"
        : "+f"(c[0]), "+f"(c[1]), "+f"(c[2]), "+f"(c[3])
        : "r"(a[0]), "r"(a[1]), "r"(a[2]), "r"(a[3]), "r"(b[0]), "r"(b[1]));
}

// ---------------- prep role (17 blocks x 256 threads) -----------------------
// pid 0..15: 64 c-rows each of g_BmatT; pid 16: alpha cols of g_S
__device__ void prep_role(int pid, float* sf, const float* __restrict__ pool,
                          const float* __restrict__ alpha) {
    const int tid = threadIdx.x;
    if (pid == 16) {
        #pragma unroll 8
        for (int it = 0; it < 64; it++) {
            int e = tid + it * 256;
            int b = e >> 6, n = e & 63;
            g_S[(size_t)b * KEXT + 1024 + n] = alpha[b * NEXP + n];
        }
        return;
    }
    for (int half = 0; half < 2; half++) {
        const int c0 = pid * 64 + half * 32;
        for (int ng = 0; ng < 4; ng++) {
            #pragma unroll
            for (int it = 0; it < 8; it++) {
                int e = tid + it * 256;
                int nl = e >> 7, i4 = e & 127;
                const float4* src = (const float4*)(pool + (size_t)(ng * 16 + nl) * POOL_DIM + c0 * 16) + i4;
                *(float4*)(sf + nl * 528 + i4 * 4) = *src;
            }
            __syncthreads();
            #pragma unroll 8
            for (int it = 0; it < 32; it++) {
                int e = tid + it * 256;
                int cl = e >> 8, j = e & 255;
                int nl = j >> 4, r = j & 15;
                g_BmatT[(size_t)(c0 + cl) * KEXT + ng * 256 + j] = sf[nl * 528 + cl * 16 + r];
            }
            __syncthreads();
        }
        #pragma unroll
        for (int it = 0; it < 8; it++) {
            int e = tid + it * 256;
            int n = e >> 5, cl = e & 31;
            sf[n * 33 + cl] = pool[(size_t)n * POOL_DIM + V_END + c0 + cl];
        }
        __syncthreads();
        #pragma unroll
        for (int it = 0; it < 8; it++) {
            int e = tid + it * 256;
            int cl = e >> 6, n = e & 63;
            g_BmatT[(size_t)(c0 + cl) * KEXT + 1024 + n] = sf[n * 33 + cl];
        }
        __syncthreads();
    }
}

// ---------------- k1: blocks 0..16 prep; 17..144 GEMM1 (64x64, 8 warps) -----
// C[256,2048] = h_A * [W_base | V]^T ; cols<1024 -> g_P, cols>=1024 -> g_S*alpha
__global__ void __launch_bounds__(256) k1_kernel(const float* __restrict__ hA,
                                                 const float* __restrict__ W,
                                                 const float* __restrict__ pool,
                                                 const float* __restrict__ alpha) {
    __shared__ __align__(128) float smem_all[12288];   // 49152 B static (3 stages)
    const int bid = blockIdx.x;
    if (bid < 17) { prep_role(bid, smem_all, pool, alpha); return; }

    const uint32_t sb = smem_u32(smem_all);
    const int gb = bid - 17;
    const int bm = gb >> 5;           // 0..3
    const int bn = gb & 31;           // 0..31
    const int tid = threadIdx.x;
    const int lane = tid & 31, warp = tid >> 5;
    const int wm = warp & 1;          // 2 row groups of 32
    const int wn = warp >> 1;         // 4 col groups of 16
    const int g = lane >> 2, tig = lane & 3;

    const uint32_t sbA = sb;                  // 3 stages x 8192
    const uint32_t sbB = sb + 3 * A_STG;      // 3 stages x 8192

    // cp.async maps (2 chunks each side per thread; 256 threads)
    const float* aPtr[2]; uint32_t aDst[2];
    const float* bPtr[2]; uint32_t bDst[2];
    #pragma unroll
    for (int q = 0; q < 2; q++) {
        int id = tid + q * 256;
        int row = id >> 3, c8 = id & 7;
        aPtr[q] = hA + (size_t)(bm * 64 + row) * D_A + c8 * 4;
        aDst[q] = swz(row * 128 + c8 * 16);
        int j = bn * 64 + row;
        const float* base = (bn < 16)
            ? (W + (size_t)j * D_A)
            : (pool + (size_t)((j - 1024) >> 4) * POOL_DIM + U_END + (size_t)((j - 1024) & 15) * D_A);
        bPtr[q] = base + c8 * 4;
        bDst[q] = swz(row * 128 + c8 * 16);
    }
    auto fill = [&](int s, int kc) {
        const int off = kc * 32;
        #pragma unroll
        for (int q = 0; q < 2; q++) {
            cpa16(sbA + s * A_STG + aDst[q], aPtr[q] + off);
            cpa16(sbB + s * B_STG1 + bDst[q], bPtr[q] + off);
        }
    };

    // ldmatrix addresses: A m32 (2 frags), B n16 (1 frag)
    uint32_t aBase[2], aXor[2], bBase, bXor;
    const uint32_t ahi = ((lane >> 4) & 1) * 16;
    const uint32_t bhi = ((lane >> 3) & 1) * 16;
    #pragma unroll
    for (int im = 0; im < 2; im++) {
        int r = wm * 32 + im * 16 + (lane & 7) + ((lane >> 3) & 1) * 8;
        aBase[im] = r * 128; aXor[im] = (r & 7) << 4;
    }
    {
        int r = wn * 16 + (lane & 7) + ((lane >> 4) & 1) * 8;
        bBase = r * 128; bXor = (r & 7) << 4;
    }

    float acc[2][2][4];
    #pragma unroll
    for (int i = 0; i < 2; i++)
        #pragma unroll
        for (int j = 0; j < 2; j++)
            #pragma unroll
            for (int e = 0; e < 4; e++) acc[i][j][e] = 0.f;

    fill(0, 0); cp_commit(); fill(1, 1); cp_commit();

    int s = 0, sw = 2;
    for (int i = 0; i < NK1; i++) {
        cp_wait<1>();
        __syncthreads();
        if (i + 2 < NK1) fill(sw, i + 2);   // global prefetch before compute
        cp_commit();
        const uint32_t sA = sbA + s * A_STG;
        const uint32_t sB = sbB + s * B_STG1;
        // software-pipelined fragments: load kk+1 while mma kk
        uint32_t a[2][2][4], b[2][4];
        LDSM4(a[0][0], sA + aBase[0] + (ahi ^ aXor[0]));
        LDSM4(a[0][1], sA + aBase[1] + (ahi ^ aXor[1]));
        LDSM4(b[0],    sB + bBase    + (bhi ^ bXor));
        #pragma unroll
        for (int kk = 0; kk < 4; kk++) {
            const int cur = kk & 1, nxt = cur ^ 1;
            if (kk < 3) {
                LDSM4(a[nxt][0], sA + aBase[0] + (((kk + 1) * 32 + ahi) ^ aXor[0]));
                LDSM4(a[nxt][1], sA + aBase[1] + (((kk + 1) * 32 + ahi) ^ aXor[1]));
                LDSM4(b[nxt],    sB + bBase    + (((kk + 1) * 32 + bhi) ^ bXor));
            }
            #pragma unroll
            for (int im = 0; im < 2; im++)
                #pragma unroll
                for (int jn = 0; jn < 2; jn++)
                    mma_tf32(acc[im][jn], a[cur][im], &b[cur][jn * 2]);
        }
        s = (s == 2) ? 0 : s + 1;
        sw = (sw == 2) ? 0 : sw + 1;
    }
    __syncthreads();

    // stage accumulators through smem, then coalesced float4 out
    float* se = smem_all;
    #pragma unroll
    for (int im = 0; im < 2; im++)
        #pragma unroll
        for (int jn = 0; jn < 2; jn++) {
            int r0 = wm * 32 + im * 16 + g;
            int c  = wn * 16 + jn * 8 + 2 * tig;
            se[r0 * EP1 + c]           = acc[im][jn][0];
            se[r0 * EP1 + c + 1]       = acc[im][jn][1];
            se[(r0 + 8) * EP1 + c]     = acc[im][jn][2];
            se[(r0 + 8) * EP1 + c + 1] = acc[im][jn][3];
        }
    __syncthreads();
    #pragma unroll
    for (int it = 0; it < 4; it++) {
        int id = tid + it * 256;
        int row = id >> 4, c4 = id & 15;
        float4 v = *(const float4*)(se + row * EP1 + c4 * 4);
        int rowg = bm * 64 + row;
        if (bn < 16) {
            ((float4*)g_P)[(size_t)rowg * 256 + bn * 16 + c4] = v;
        } else {
            int n = (bn - 16) * 4 + (c4 >> 2);
            float a = alpha[rowg * NEXP + n];
            v.x *= a; v.y *= a; v.z *= a; v.w *= a;
            ((float4*)g_S)[(size_t)rowg * 272 + (bn - 16) * 16 + c4] = v;
        }
    }
}

// ---------------- k2: GEMM2 64x32, 8 warps, 4 stages -------------------------
// X = hA + gamma*(S@BmatT^T + P + b_base)
__global__ void __launch_bounds__(256) k2_kernel(const float* __restrict__ hA,
                                                 const float* __restrict__ bbase,
                                                 const float* __restrict__ gamma_p) {
    __shared__ __align__(128) float smem_all[12288];   // 49152 B (4 stages x 12KB)
    const uint32_t sb = smem_u32(smem_all);
    const int bid = blockIdx.x;
    const int bm = bid >> 5;          // 0..3
    const int bn = bid & 31;          // 0..31
    const int tid = threadIdx.x;
    const int lane = tid & 31, warp = tid >> 5;
    const int wm = warp & 3;          // 4 row groups of 16
    const int wn = warp >> 2;         // 2 col groups of 16
    const int g = lane >> 2, tig = lane & 3;

    const uint32_t sbA = sb;                  // 4 stages x 8192
    const uint32_t sbB = sb + 4 * A_STG;      // 4 stages x 4096

    const float* aPtr[2]; uint32_t aDst[2];
    #pragma unroll
    for (int q = 0; q < 2; q++) {
        int id = tid + q * 256;
        int row = id >> 3, c8 = id & 7;
        aPtr[q] = g_S + (size_t)(bm * 64 + row) * KEXT + c8 * 4;
        aDst[q] = swz(row * 128 + c8 * 16);
    }
    const float* bPtr; uint32_t bDst;
    {
        int row = tid >> 3, c8 = tid & 7;
        bPtr = g_BmatT + (size_t)(bn * 32 + row) * KEXT + c8 * 4;
        bDst = swz(row * 128 + c8 * 16);
    }
    auto fill = [&](int s, int kc) {
        const int off = kc * 32;
        #pragma unroll
        for (int q = 0; q < 2; q++)
            cpa16(sbA + s * A_STG + aDst[q], aPtr[q] + off);
        cpa16(sbB + s * B_STG2 + bDst, bPtr + off);
    };

    uint32_t aBase, aXor, bBase, bXor;
    const uint32_t ahi = ((lane >> 4) & 1) * 16;
    const uint32_t bhi = ((lane >> 3) & 1) * 16;
    {
        int r = wm * 16 + (lane & 7) + ((lane >> 3) & 1) * 8;
        aBase = r * 128; aXor = (r & 7) << 4;
    }
    {
        int r = wn * 16 + (lane & 7) + ((lane >> 4) & 1) * 8;
        bBase = r * 128; bXor = (r & 7) << 4;
    }

    float acc[2][4];
    #pragma unroll
    for (int j = 0; j < 2; j++)
        #pragma unroll
        for (int e = 0; e < 4; e++) acc[j][e] = 0.f;

    fill(0, 0); cp_commit(); fill(1, 1); cp_commit(); fill(2, 2); cp_commit();

    for (int i = 0; i < NK2; i++) {
        cp_wait<2>();
        __syncthreads();
        if (i + 3 < NK2) fill((i + 3) & 3, i + 3);
        cp_commit();
        const int s = i & 3;
        const uint32_t sA = sbA + s * A_STG;
        const uint32_t sB = sbB + s * B_STG2;
        // software-pipelined fragments
        uint32_t a[2][4], b[2][4];
        LDSM4(a[0], sA + aBase + (ahi ^ aXor));
        LDSM4(b[0], sB + bBase + (bhi ^ bXor));
        #pragma unroll
        for (int kk = 0; kk < 4; kk++) {
            const int cur = kk & 1, nxt = cur ^ 1;
            if (kk < 3) {
                LDSM4(a[nxt], sA + aBase + (((kk + 1) * 32 + ahi) ^ aXor));
                LDSM4(b[nxt], sB + bBase + (((kk + 1) * 32 + bhi) ^ bXor));
            }
            #pragma unroll
            for (int jn = 0; jn < 2; jn++)
                mma_tf32(acc[jn], a[cur], &b[cur][jn * 2]);
        }
    }
    __syncthreads();

    float* se = smem_all;
    #pragma unroll
    for (int jn = 0; jn < 2; jn++) {
        int r0 = wm * 16 + g;
        int c  = wn * 16 + jn * 8 + 2 * tig;
        se[r0 * EP2 + c]           = acc[jn][0];
        se[r0 * EP2 + c + 1]       = acc[jn][1];
        se[(r0 + 8) * EP2 + c]     = acc[jn][2];
        se[(r0 + 8) * EP2 + c + 1] = acc[jn][3];
    }
    __syncthreads();
    const float gam = *gamma_p;
    #pragma unroll
    for (int it = 0; it < 2; it++) {
        int id = tid + it * 256;
        int row = id >> 3, c4 = id & 7;
        float4 v = *(const float4*)(se + row * EP2 + c4 * 4);
        int rowg = bm * 64 + row;
        int cc4 = bn * 8 + c4;
        float4 p4 = ((const float4*)g_P)[(size_t)rowg * 256 + cc4];
        float4 b4 = ((const float4*)bbase)[cc4];
        float4 h4 = ((const float4*)hA)[(size_t)rowg * 256 + cc4];
        float4 x;
        x.x = h4.x + gam * (v.x + p4.x + b4.x);
        x.y = h4.y + gam * (v.y + p4.y + b4.y);
        x.z = h4.z + gam * (v.z + p4.z + b4.z);
        x.w = h4.w + gam * (v.w + p4.w + b4.w);
        ((float4*)g_X)[(size_t)rowg * 256 + cc4] = x;
        float s2  = x.x + x.y + x.z + x.w;
        float ss2 = x.x * x.x + x.y * x.y + x.z * x.z + x.w * x.w;
        #pragma unroll
        for (int off = 4; off; off >>= 1) {
            s2  += __shfl_xor_sync(0xffffffffu, s2, off);
            ss2 += __shfl_xor_sync(0xffffffffu, ss2, off);
        }
        if ((tid & 7) == 0) g_part[rowg * 32 + bn] = make_float2(s2, ss2);
    }
}

// ---------------- LayerNorm: warp per row, normalize-only ----------------
__global__ void __launch_bounds__(256) ln_kernel(const float* __restrict__ lns,
                                                 const float* __restrict__ lnb,
                                                 float* __restrict__ out) {
    const int tid = threadIdx.x;
    const int lane = tid & 31;
    const int row = blockIdx.x * 8 + (tid >> 5);
    float2 p = g_part[row * 32 + lane];
    float s = p.x, ss = p.y;
    #pragma unroll
    for (int off = 16; off; off >>= 1) {
        s  += __shfl_xor_sync(0xffffffffu, s, off);
        ss += __shfl_xor_sync(0xffffffffu, ss, off);
    }
    const float mean = s * (1.f / 1024.f);
    const float inv  = rsqrtf(ss * (1.f / 1024.f) - mean * mean + LN_EPS);
    #pragma unroll
    for (int j = 0; j < 8; j++) {
        int c4 = lane + j * 32;
        float4 x = ((const float4*)g_X)[(size_t)row * 256 + c4];
        float4 sc = ((const float4*)lns)[c4];
        float4 bi = ((const float4*)lnb)[c4];
        float4 o;
        o.x = (x.x - mean) * inv * sc.x + bi.x;
        o.y = (x.y - mean) * inv * sc.y + bi.y;
        o.z = (x.z - mean) * inv * sc.z + bi.z;
        o.w = (x.w - mean) * inv * sc.w + bi.w;
        ((float4*)out)[(size_t)row * 256 + c4] = o;
    }
}

// ---------------- launch: kernel launches ONLY ----------------
extern "C" void kernel_launch(void* const* d_in, const int* in_sizes, int n_in,
                              void* d_out, int out_size) {
    const float* hA    = (const float*)d_in[0];
    const float* pool  = (const float*)d_in[1];
    const float* alpha = (const float*)d_in[2];
    const float* W     = (const float*)d_in[3];
    const float* bb    = (const float*)d_in[4];
    const float* gamma = (const float*)d_in[5];
    const float* lns   = (const float*)d_in[6];
    const float* lnb   = (const float*)d_in[7];
    float* out = (float*)d_out;

    k1_kernel<<<145, 256>>>(hA, W, pool, alpha);
    k2_kernel<<<128, 256>>>(hA, bb, gamma);
    ln_kernel<<<32, 256>>>(lns, lnb, out);
}